// round 16
// baseline (speedup 1.0000x reference)
#include <cuda_runtime.h>
#include <cuda_fp16.h>
#include <cstdint>

// Problem constants (fixed by the dataset)
#define BT_  1024   // B*T = 4*256
#define IN_  512
#define OUT_ 512

// Scratch (no cudaMalloc allowed): decoded fp32 operands, k-major.
__device__ float g_xT[IN_ * BT_];    // [k][m]  2 MB
__device__ float g_wT[IN_ * OUT_];   // [k][n]  1 MB

// ---------------------------------------------------------------------------
// Packed f32x2 FMA (Blackwell): two independent fp32 FMAs, each rounded
// exactly like scalar FFMA -> preserves bit-exact sequential accumulation.
// ---------------------------------------------------------------------------
__device__ __forceinline__ unsigned long long fma2(unsigned long long a,
                                                   unsigned long long b,
                                                   unsigned long long c) {
    unsigned long long d;
    asm("fma.rn.f32x2 %0, %1, %2, %3;" : "=l"(d) : "l"(a), "l"(b), "l"(c));
    return d;
}
__device__ __forceinline__ unsigned long long dup2(float v) {
    unsigned long long d;
    asm("mov.b64 %0, {%1, %1};" : "=l"(d) : "f"(v));
    return d;
}
__device__ __forceinline__ uint32_t sptr(const void* p) {
    return (uint32_t)__cvta_generic_to_shared(p);
}
__device__ __forceinline__ void cpa16(uint32_t dst, const void* src) {
    asm volatile("cp.async.cg.shared.global [%0], [%1], 16;" :: "r"(dst), "l"(src));
}

// ---------------------------------------------------------------------------
// Kernel 1: decode pulse bits -> fp16-exact fp32 via FFMA-imm dot product.
// Pulse bits are EXACT {0.0f, 1.0f}, so u = sum(bit_k * 2^k) is exact fp32;
// adding 2^23 places the integer in the mantissa -> u = bits(f) & 0xFFFF
// (no F2I). 15 FFMA-imm (rt=1) + 1 AND replaces ~32 shift/or (rt=2).
// Memory pattern unchanged from the proven R11 transpose (odd-pitch smem,
// conflict-free both phases, 2KB-contiguous reads, 64B k-major writes).
// ---------------------------------------------------------------------------
__device__ __forceinline__ float dec16f(const float4* p) {
    float4 a = p[0], b = p[1], c = p[2], d = p[3];
    // bits 0-3 (with 2^23 bias folded in) ... exact: all integers < 2^24
    float t0 = fmaf(a.y, 2.f, a.x + 8388608.f);
    float t1 = fmaf(a.w, 2.f, a.z);
    float q0 = fmaf(t1, 4.f, t0);
    float t2 = fmaf(b.y, 2.f, b.x);
    float t3 = fmaf(b.w, 2.f, b.z);
    float q1 = fmaf(t3, 4.f, t2);
    float o0 = fmaf(q1, 16.f, q0);        // bits 0-7 + bias
    float t4 = fmaf(c.y, 2.f, c.x);
    float t5 = fmaf(c.w, 2.f, c.z);
    float q2 = fmaf(t5, 4.f, t4);
    float t6 = fmaf(d.y, 2.f, d.x);
    float t7 = fmaf(d.w, 2.f, d.z);
    float q3 = fmaf(t7, 4.f, t6);
    float o1 = fmaf(q3, 16.f, q2);        // bits 8-15
    float f  = fmaf(o1, 256.f, o0);       // = 2^23 + u  (exact)
    unsigned u = __float_as_uint(f) & 0xFFFFu;
    return __half2float(__ushort_as_half((unsigned short)u));
}

__global__ __launch_bounds__(128) void decode_kernel(const float4* __restrict__ xp,
                                                     const float4* __restrict__ wp) {
    __shared__ float S[64][67];   // [k][m], odd pitch -> conflict-free both ways

    const int b = blockIdx.x;
    const float4* src;
    float* dstT;
    int mbase, kbase, width;
    if (b < 256) {                       // X: 32 mblk x 8 kblk
        mbase = (b >> 3) * 32; kbase = (b & 7) * 64;
        src = xp; dstT = g_xT; width = BT_;
    } else {                             // W: 16 mblk x 8 kblk
        int b2 = b - 256;
        mbase = (b2 >> 3) * 32; kbase = (b2 & 7) * 64;
        src = wp; dstT = g_wT; width = OUT_;
    }

    const int t = threadIdx.x;

    // Phase A: 16 elements/thread; warp reads 2KB-contiguous streams.
#pragma unroll
    for (int j = 0; j < 8; ++j) {
        int idx = t + 128 * j;           // 0..1023
        int m0 = idx >> 6, k0 = idx & 63;
        int m1 = m0 + 16;
        const float4* p0 = src + ((size_t)(mbase + m0) * IN_ + kbase + k0) * 4;
        const float4* p1 = src + ((size_t)(mbase + m1) * IN_ + kbase + k0) * 4;
        S[k0][m0] = dec16f(p0);
        S[k0][m1] = dec16f(p1);
    }
    __syncthreads();

    // Phase B: thread t -> k-row (t&63), half (t>>6)*16; write 64B runs.
    const int kk = t & 63;
    const int part = (t >> 6) * 16;
    float4 r[4];
#pragma unroll
    for (int g = 0; g < 4; ++g)
        r[g] = make_float4(S[kk][part + 4 * g + 0], S[kk][part + 4 * g + 1],
                           S[kk][part + 4 * g + 2], S[kk][part + 4 * g + 3]);
    float4* d = reinterpret_cast<float4*>(
        dstT + (size_t)(kbase + kk) * width + mbase + part);
#pragma unroll
    for (int g = 0; g < 4; ++g) d[g] = r[g];
}

// ---------------------------------------------------------------------------
// Kernel 2 (mainloop = measured-best R10/R15): bit-exact sequential-k GEMM +
// RNE fp16 + pulse encode. Tile 64x64, 128 threads, TM=8 x TN=4, M-paired
// f32x2 accs; per k: 3 LDS.128 + 4 dup-movs + 16 fma2 with k+1 register-
// fragment double buffering; cp.async BK=32 double-buffered fills.
// NEW: epilogue expands 4 bits at a time through a 16-entry float4 smem LUT
// (SHF+LOP+LDS.128+STG.128 per quad vs ~12 ALU before).
// ---------------------------------------------------------------------------
#define BM  64
#define BN  64
#define BK  32
#define NT  (IN_ / BK)   // 16 tiles
#define PX  68           // smem pitch: 64 + 4 floats (rows 16B-aligned)

__global__ __launch_bounds__(128) void gemm_enc_kernel(float* __restrict__ out) {
    __shared__ __align__(16) float Xs[2][BK][PX];   // [k][m]
    __shared__ __align__(16) float Ws[2][BK][PX];   // [k][n]
    __shared__ __align__(16) float4 LUT[16];        // nibble -> 4 pulse floats

    const int tid  = threadIdx.x;
    const int row0 = blockIdx.y * BM;
    const int col0 = blockIdx.x * BN;

    if (tid < 16)
        LUT[tid] = make_float4((tid & 1) ? 1.f : 0.f, (tid & 2) ? 1.f : 0.f,
                               (tid & 4) ? 1.f : 0.f, (tid & 8) ? 1.f : 0.f);
    // visibility of LUT is covered by the mainloop's __syncthreads.

    const int rg = tid >> 4;    // 0..7  -> rows 8*rg .. 8*rg+7
    const int cg = tid & 15;    // 0..15 -> cols 4*cg .. 4*cg+3

    // acc[p][c] = (C[8rg+2p][4cg+c], C[8rg+2p+1][4cg+c])
    unsigned long long acc[4][4] = {};

    auto fill = [&](int buf, int t) {
        const int kt = t * BK;
        // 512 16B-chunks per array (32k x 16), 4 per thread each
#pragma unroll
        for (int i = 0; i < 4; ++i) {
            int j = tid + 128 * i, k = j >> 4, c = j & 15;
            cpa16(sptr(&Xs[buf][k][c * 4]),
                  g_xT + (size_t)(kt + k) * BT_ + row0 + c * 4);
            cpa16(sptr(&Ws[buf][k][c * 4]),
                  g_wT + (size_t)(kt + k) * OUT_ + col0 + c * 4);
        }
        asm volatile("cp.async.commit_group;");
    };

    fill(0, 0);

    int buf = 0;
    for (int t = 0; t < NT; ++t) {
        if (t + 1 < NT) {
            fill(buf ^ 1, t + 1);
            asm volatile("cp.async.wait_group 1;");   // tile t's fill done
        } else {
            asm volatile("cp.async.wait_group 0;");
        }
        __syncthreads();

        // --- compute: strictly ascending k; k+1 frags prefetched into regs ---
        ulonglong2 xa[2], xb[2];
        float4     wq[2];
        xa[0] = *reinterpret_cast<const ulonglong2*>(&Xs[buf][0][8 * rg]);
        xb[0] = *reinterpret_cast<const ulonglong2*>(&Xs[buf][0][8 * rg + 4]);
        wq[0] = *reinterpret_cast<const float4*>(&Ws[buf][0][4 * cg]);
#pragma unroll
        for (int k = 0; k < BK; ++k) {
            const int cur = k & 1, nxt = cur ^ 1;
            if (k + 1 < BK) {
                xa[nxt] = *reinterpret_cast<const ulonglong2*>(&Xs[buf][k + 1][8 * rg]);
                xb[nxt] = *reinterpret_cast<const ulonglong2*>(&Xs[buf][k + 1][8 * rg + 4]);
                wq[nxt] = *reinterpret_cast<const float4*>(&Ws[buf][k + 1][4 * cg]);
            }
            unsigned long long wd[4];
            wd[0] = dup2(wq[cur].x); wd[1] = dup2(wq[cur].y);
            wd[2] = dup2(wq[cur].z); wd[3] = dup2(wq[cur].w);
            unsigned long long xr[4] = {xa[cur].x, xa[cur].y, xb[cur].x, xb[cur].y};
#pragma unroll
            for (int p = 0; p < 4; ++p)
#pragma unroll
                for (int c = 0; c < 4; ++c)
                    acc[p][c] = fma2(xr[p], wd[c], acc[p][c]);
        }
        __syncthreads();   // all reads of buf done before it is refilled
        buf ^= 1;
    }

    // --- fused epilogue: fp32 -> fp16 (RNE) -> 16 pulse bits per output ---
    // Nibble-LUT expansion: per output quad = SHF+LOP+LDS.128+STG.128.
    // Each thread writes 8 rows x 4 consecutive cols = 256B contiguous runs.
    const int cb = col0 + cg * 4;
#pragma unroll
    for (int p = 0; p < 4; ++p) {
        unsigned u[2][4];
#pragma unroll
        for (int c = 0; c < 4; ++c) {
            float lo, hi;
            asm("mov.b64 {%0, %1}, %2;" : "=f"(lo), "=f"(hi) : "l"(acc[p][c]));
            u[0][c] = __half_as_ushort(__float2half_rn(lo));
            u[1][c] = __half_as_ushort(__float2half_rn(hi));
        }
#pragma unroll
        for (int i = 0; i < 2; ++i) {
            int r = row0 + 8 * rg + 2 * p + i;
            float4* dst = reinterpret_cast<float4*>(out + ((size_t)r * OUT_ + cb) * 16);
#pragma unroll
            for (int c = 0; c < 4; ++c)
#pragma unroll
                for (int q4 = 0; q4 < 4; ++q4)
                    dst[c * 4 + q4] = LUT[(u[i][c] >> (4 * q4)) & 0xFu];
        }
    }
}

// ---------------------------------------------------------------------------
extern "C" void kernel_launch(void* const* d_in, const int* in_sizes, int n_in,
                              void* d_out, int out_size) {
    const float4* xp = (const float4*)d_in[0];   // x_pulse [4,256,512,16]
    const float4* wp = (const float4*)d_in[1];   // w_pulse [512,512,16]
    float* out = (float*)d_out;                  // [4,256,512,16]
    (void)in_sizes; (void)n_in; (void)out_size;

    // 1) decode + smem transpose: 256 X-blocks + 128 W-blocks, 128 threads
    decode_kernel<<<384, 128>>>(xp, wp);

    // 2) fused bit-exact GEMM + RNE fp16 + pulse-bit encode
    dim3 grid(OUT_ / BN, BT_ / BM);              // (8, 16) = 128 CTAs
    gemm_enc_kernel<<<grid, 128>>>(out);
}

// round 17
// speedup vs baseline: 1.0617x; 1.0617x over previous
#include <cuda_runtime.h>
#include <cuda_fp16.h>
#include <cstdint>

// Problem constants (fixed by the dataset)
#define BT_  1024   // B*T = 4*256
#define IN_  512
#define OUT_ 512

// Scratch (no cudaMalloc allowed): decoded fp32 operands, k-major.
__device__ float g_xT[IN_ * BT_];    // [k][m]  2 MB
__device__ float g_wT[IN_ * OUT_];   // [k][n]  1 MB

// ---------------------------------------------------------------------------
// Packed f32x2 FMA (Blackwell): two independent fp32 FMAs, each rounded
// exactly like scalar FFMA -> preserves bit-exact sequential accumulation.
// ---------------------------------------------------------------------------
__device__ __forceinline__ unsigned long long fma2(unsigned long long a,
                                                   unsigned long long b,
                                                   unsigned long long c) {
    unsigned long long d;
    asm("fma.rn.f32x2 %0, %1, %2, %3;" : "=l"(d) : "l"(a), "l"(b), "l"(c));
    return d;
}
__device__ __forceinline__ unsigned long long dup2(float v) {
    unsigned long long d;
    asm("mov.b64 %0, {%1, %1};" : "=l"(d) : "f"(v));
    return d;
}
__device__ __forceinline__ uint32_t sptr(const void* p) {
    return (uint32_t)__cvta_generic_to_shared(p);
}
__device__ __forceinline__ void cpa16(uint32_t dst, const void* src) {
    asm volatile("cp.async.cg.shared.global [%0], [%1], 16;" :: "r"(dst), "l"(src));
}

// ---------------------------------------------------------------------------
// Kernel 1 (MEASURED 9.3us, R15): decode pulse bits -> fp16-exact fp32,
// transposed to k-major via smem with ODD pitch (67): column-stores (A) and
// row-reads (B) both bank-conflict-free; GMEM reads 2KB-contiguous per warp,
// GMEM writes coalesced 64B k-major runs.
// Pulse floats are exactly 0.0f or 1.0f, so bit 23 of the raw word is the bit.
// ---------------------------------------------------------------------------
__device__ __forceinline__ unsigned dec16(const uint4* p) {
    uint4 v[4];
#pragma unroll
    for (int q = 0; q < 4; ++q) v[q] = p[q];
    unsigned u = 0u;
#pragma unroll
    for (int q = 0; q < 4; ++q) {
        u |= ((v[q].x >> 23) & 1u) << (4 * q + 0);
        u |= ((v[q].y >> 23) & 1u) << (4 * q + 1);
        u |= ((v[q].z >> 23) & 1u) << (4 * q + 2);
        u |= ((v[q].w >> 23) & 1u) << (4 * q + 3);
    }
    return u;
}

__global__ __launch_bounds__(128) void decode_kernel(const uint4* __restrict__ xp,
                                                     const uint4* __restrict__ wp) {
    __shared__ float S[64][67];   // [k][m], odd pitch -> conflict-free both ways

    const int b = blockIdx.x;
    const uint4* src;
    float* dstT;
    int mbase, kbase, width;
    if (b < 256) {                       // X: 32 mblk x 8 kblk
        mbase = (b >> 3) * 32; kbase = (b & 7) * 64;
        src = xp; dstT = g_xT; width = BT_;
    } else {                             // W: 16 mblk x 8 kblk
        int b2 = b - 256;
        mbase = (b2 >> 3) * 32; kbase = (b2 & 7) * 64;
        src = wp; dstT = g_wT; width = OUT_;
    }

    const int t = threadIdx.x;

    // Phase A: 16 elements/thread; warp reads 2KB-contiguous streams.
#pragma unroll
    for (int j = 0; j < 8; ++j) {
        int idx = t + 128 * j;           // 0..1023
        int m0 = idx >> 6, k0 = idx & 63;
        int m1 = m0 + 16;
        const uint4* p0 = src + ((size_t)(mbase + m0) * IN_ + kbase + k0) * 4;
        const uint4* p1 = src + ((size_t)(mbase + m1) * IN_ + kbase + k0) * 4;
        unsigned u0 = dec16(p0);
        unsigned u1 = dec16(p1);
        S[k0][m0] = __half2float(__ushort_as_half((unsigned short)u0));
        S[k0][m1] = __half2float(__ushort_as_half((unsigned short)u1));
    }
    __syncthreads();

    // Phase B: thread t -> k-row (t&63), half (t>>6)*16; write 64B runs.
    const int kk = t & 63;
    const int part = (t >> 6) * 16;
    float4 r[4];
#pragma unroll
    for (int g = 0; g < 4; ++g)
        r[g] = make_float4(S[kk][part + 4 * g + 0], S[kk][part + 4 * g + 1],
                           S[kk][part + 4 * g + 2], S[kk][part + 4 * g + 3]);
    float4* d = reinterpret_cast<float4*>(
        dstT + (size_t)(kbase + kk) * width + mbase + part);
#pragma unroll
    for (int g = 0; g < 4; ++g) d[g] = r[g];
}

// ---------------------------------------------------------------------------
// Kernel 2: bit-exact sequential-k GEMM + RNE fp16 + pulse encode.
// Identical to the measured-best R15 kernel (27.6us) EXCEPT the mainloop
// uses ONE __syncthreads per tile: the fill for tile t+1 is issued AFTER
// the tile-t publish barrier, so the next iteration's publish barrier
// already separates the last read of a buffer from its refill (per-warp
// program order: compute(t) < sync(t+1) < fill(t+2)). The fill still hides
// under a full tile of compute (~2700cy >> LDG latency).
// Tile 64x64, 128 threads, TM=8 x TN=4, M-paired f32x2 accs; per k:
// 3 LDS.128 + 4 dup-movs + 16 fma2 with k+1 register-fragment double
// buffering; cp.async BK=32 double-buffered fills; ALU bits4 epilogue.
// ---------------------------------------------------------------------------
#define BM  64
#define BN  64
#define BK  32
#define NT  (IN_ / BK)   // 16 tiles
#define PX  68           // smem pitch: 64 + 4 floats (rows 16B-aligned)

__device__ __forceinline__ float4 bits4(unsigned u, int s) {
    float4 f;
    f.x = __uint_as_float(((u >> (s + 0)) & 1u) * 0x3F800000u);
    f.y = __uint_as_float(((u >> (s + 1)) & 1u) * 0x3F800000u);
    f.z = __uint_as_float(((u >> (s + 2)) & 1u) * 0x3F800000u);
    f.w = __uint_as_float(((u >> (s + 3)) & 1u) * 0x3F800000u);
    return f;
}

__global__ __launch_bounds__(128) void gemm_enc_kernel(float* __restrict__ out) {
    __shared__ __align__(16) float Xs[2][BK][PX];   // [k][m]
    __shared__ __align__(16) float Ws[2][BK][PX];   // [k][n]

    const int tid  = threadIdx.x;
    const int row0 = blockIdx.y * BM;
    const int col0 = blockIdx.x * BN;

    const int rg = tid >> 4;    // 0..7  -> rows 8*rg .. 8*rg+7
    const int cg = tid & 15;    // 0..15 -> cols 4*cg .. 4*cg+3

    // acc[p][c] = (C[8rg+2p][4cg+c], C[8rg+2p+1][4cg+c])
    unsigned long long acc[4][4] = {};

    auto fill = [&](int buf, int t) {
        const int kt = t * BK;
        // 512 16B-chunks per array (32k x 16), 4 per thread each
#pragma unroll
        for (int i = 0; i < 4; ++i) {
            int j = tid + 128 * i, k = j >> 4, c = j & 15;
            cpa16(sptr(&Xs[buf][k][c * 4]),
                  g_xT + (size_t)(kt + k) * BT_ + row0 + c * 4);
            cpa16(sptr(&Ws[buf][k][c * 4]),
                  g_wT + (size_t)(kt + k) * OUT_ + col0 + c * 4);
        }
        asm volatile("cp.async.commit_group;");
    };

    fill(0, 0);

    int buf = 0;
    for (int t = 0; t < NT; ++t) {
        // fill(t) is the only outstanding group here
        asm volatile("cp.async.wait_group 0;");
        __syncthreads();   // publish tile t; also: all warps finished reading
                           // buf^1 (tile t-1), so it is safe to refill below.
        if (t + 1 < NT) fill(buf ^ 1, t + 1);

        // --- compute: strictly ascending k; k+1 frags prefetched into regs ---
        ulonglong2 xa[2], xb[2];
        float4     wq[2];
        xa[0] = *reinterpret_cast<const ulonglong2*>(&Xs[buf][0][8 * rg]);
        xb[0] = *reinterpret_cast<const ulonglong2*>(&Xs[buf][0][8 * rg + 4]);
        wq[0] = *reinterpret_cast<const float4*>(&Ws[buf][0][4 * cg]);
#pragma unroll
        for (int k = 0; k < BK; ++k) {
            const int cur = k & 1, nxt = cur ^ 1;
            if (k + 1 < BK) {
                xa[nxt] = *reinterpret_cast<const ulonglong2*>(&Xs[buf][k + 1][8 * rg]);
                xb[nxt] = *reinterpret_cast<const ulonglong2*>(&Xs[buf][k + 1][8 * rg + 4]);
                wq[nxt] = *reinterpret_cast<const float4*>(&Ws[buf][k + 1][4 * cg]);
            }
            unsigned long long wd[4];
            wd[0] = dup2(wq[cur].x); wd[1] = dup2(wq[cur].y);
            wd[2] = dup2(wq[cur].z); wd[3] = dup2(wq[cur].w);
            unsigned long long xr[4] = {xa[cur].x, xa[cur].y, xb[cur].x, xb[cur].y};
#pragma unroll
            for (int p = 0; p < 4; ++p)
#pragma unroll
                for (int c = 0; c < 4; ++c)
                    acc[p][c] = fma2(xr[p], wd[c], acc[p][c]);
        }
        buf ^= 1;   // no trailing barrier: next publish barrier protects reuse
    }

    // --- fused epilogue: fp32 -> fp16 (RNE) -> 16 pulse bits per output ---
    // Each thread writes 8 rows x 4 consecutive cols = 256B contiguous runs.
    const int cb = col0 + cg * 4;
#pragma unroll
    for (int p = 0; p < 4; ++p) {
        unsigned short u[2][4];
#pragma unroll
        for (int c = 0; c < 4; ++c) {
            float lo, hi;
            asm("mov.b64 {%0, %1}, %2;" : "=f"(lo), "=f"(hi) : "l"(acc[p][c]));
            u[0][c] = __half_as_ushort(__float2half_rn(lo));
            u[1][c] = __half_as_ushort(__float2half_rn(hi));
        }
#pragma unroll
        for (int i = 0; i < 2; ++i) {
            int r = row0 + 8 * rg + 2 * p + i;
            float4* dst = reinterpret_cast<float4*>(out + ((size_t)r * OUT_ + cb) * 16);
#pragma unroll
            for (int c = 0; c < 4; ++c)
#pragma unroll
                for (int q4 = 0; q4 < 4; ++q4)
                    dst[c * 4 + q4] = bits4(u[i][c], 4 * q4);
        }
    }
}

// ---------------------------------------------------------------------------
extern "C" void kernel_launch(void* const* d_in, const int* in_sizes, int n_in,
                              void* d_out, int out_size) {
    const uint4* xp = (const uint4*)d_in[0];   // x_pulse [4,256,512,16]
    const uint4* wp = (const uint4*)d_in[1];   // w_pulse [512,512,16]
    float* out = (float*)d_out;                // [4,256,512,16]
    (void)in_sizes; (void)n_in; (void)out_size;

    // 1) decode + smem transpose: 256 X-blocks + 128 W-blocks, 128 threads
    decode_kernel<<<384, 128>>>(xp, wp);

    // 2) fused bit-exact GEMM + RNE fp16 + pulse-bit encode
    dim3 grid(OUT_ / BN, BT_ / BM);            // (8, 16) = 128 CTAs
    gemm_enc_kernel<<<grid, 128>>>(out);
}